// round 15
// baseline (speedup 1.0000x reference)
#include <cuda_runtime.h>
#include <cuda_fp16.h>
#include <cstdint>

// ---------------- problem constants ----------------
#define BATCH 4096
#define DIM   2048
#define NK    8
#define H2    64

// ---------------- tiling ----------------
#define BM     64
#define BN     128
#define KC     64
#define NCHUNK (DIM / KC)        // 32
#define GX     (DIM / BN)        // 16 d-blocks
#define GYT    72                // max m-tiles
#define NSTAGE 3
#define NJOBS  (GX * GYT)        // 1152

#define ROW_B   128
#define A_T     (BM * ROW_B)     // 8192
#define B_T     (BN * ROW_B)     // 16384
#define STAGE_B (A_T + B_T)      // 24576
#define SMEM_TOTAL (NSTAGE * STAGE_B)   // 73728 (x3 CTAs resident)

// persistent grid: all CTAs co-resident (3/SM x 148 SMs)
#define NCTA 444
// cvt: per chunk 163840 units (x: 32768, W: 131072); share ~369/CTA
#define CHUNK_UNITS 163840
#define SHARE_BASE  369          // 444*369 = 163836, first 4 CTAs +1

// ---------------- device scratch ----------------
__device__ int g_perm[BATCH];
__device__ int g_tile_k[GYT];
__device__ int g_tile_row0[GYT];
__device__ int g_tile_rend[GYT];
__device__ int g_ntiles;
__device__ int g_prep;
__device__ int g_done[NCHUNK];
__device__ uint4 g_xh[BATCH * DIM / 8];               // 16.8 MB fp16
__device__ uint4 g_wh[(size_t)NK * DIM * DIM / 8];    // 67 MB fp16, [k][d][j]

// ---------------- PTX helpers ----------------
__device__ __forceinline__ uint32_t smem_u32(const void* p) {
    uint32_t a;
    asm("{ .reg .u64 t; cvta.to.shared.u64 t, %1; cvt.u32.u64 %0, t; }" : "=r"(a) : "l"(p));
    return a;
}
__device__ __forceinline__ void cpasync16(uint32_t dst, const void* src) {
    asm volatile("{ .reg .u64 g; cvta.to.global.u64 g, %1; "
                 "cp.async.cg.shared.global [%0], [g], 16; }"
                 :: "r"(dst), "l"(src) : "memory");
}
#define CP_COMMIT() asm volatile("cp.async.commit_group;" ::: "memory")
#define CP_WAIT1()  asm volatile("cp.async.wait_group 1;" ::: "memory")

__device__ __forceinline__ void ldsm4(uint32_t* r, uint32_t addr) {
    asm volatile("ldmatrix.sync.aligned.m8n8.x4.shared.b16 {%0,%1,%2,%3}, [%4];"
                 : "=r"(r[0]), "=r"(r[1]), "=r"(r[2]), "=r"(r[3]) : "r"(addr));
}
__device__ __forceinline__ void mma_f16(float* c, const uint32_t* a, const uint32_t* b) {
    asm volatile(
        "mma.sync.aligned.m16n8k16.row.col.f32.f16.f16.f32 "
        "{%0,%1,%2,%3}, {%4,%5,%6,%7}, {%8,%9}, {%0,%1,%2,%3};"
        : "+f"(c[0]), "+f"(c[1]), "+f"(c[2]), "+f"(c[3])
        : "r"(a[0]), "r"(a[1]), "r"(a[2]), "r"(a[3]), "r"(b[0]), "r"(b[1]));
}
__device__ __forceinline__ uint32_t packh2(float f0, float f1) {
    __half2 p = __floats2half2_rn(f0, f1);
    return *reinterpret_cast<uint32_t*>(&p);
}
__device__ __forceinline__ uint4 pack8(float4 v0, float4 v1) {
    uint4 h;
    h.x = packh2(v0.x, v0.y);
    h.y = packh2(v0.z, v0.w);
    h.z = packh2(v1.x, v1.y);
    h.w = packh2(v1.z, v1.w);
    return h;
}

// ---------------- reset (per launch) ----------------
__global__ void reset_kernel() {
    int t = threadIdx.x;
    if (t < NCHUNK) g_done[t] = 0;
    if (t == NCHUNK) g_prep = 0;
}

// ---------------- fused persistent kernel ----------------
__global__ void __launch_bounds__(256, 3) fused_kernel(
    const float* __restrict__ x, const float* __restrict__ W1,
    const float* __restrict__ intention, const float* __restrict__ W2,
    const float* __restrict__ b2, const float* __restrict__ b1,
    const float* __restrict__ W3, const float* __restrict__ b3,
    float* __restrict__ out) {
    int p = blockIdx.x;
    int t = threadIdx.x;
    int lane = t & 31;
    int wid  = t >> 5;

    // cvt share bounds for this CTA
    int ss = p * SHARE_BASE + (p < 4 ? p : 4);
    int se = ss + SHARE_BASE + (p < 4 ? 1 : 0);
    const float4* xin = (const float4*)x;
    const float4* win = (const float4*)W1;

    auto cvt_share = [&](int jc) {
#pragma unroll
        for (int rep = 0; rep < 2; rep++) {
            int u = ss + rep * 256 + t;
            if (u < se) {
                if (u < 32768) {
                    int sample = u >> 3, g8 = u & 7;
                    int gran = jc * 8 + g8;
                    size_t s = (size_t)sample * 512 + (size_t)gran * 2;
                    g_xh[(size_t)sample * 256 + gran] =
                        pack8(__ldg(xin + s), __ldg(xin + s + 1));
                } else {
                    int v = u - 32768;
                    int j8 = v & 7;
                    int rowidx = v >> 3;               // k*2048 + d
                    int kk = rowidx >> 11, d = rowidx & (DIM - 1);
                    size_t s = ((size_t)((d << 3) | kk)) * 512 + (size_t)(jc * 8 + j8) * 2;
                    g_wh[(size_t)rowidx * 256 + jc * 8 + j8] =
                        pack8(__ldg(win + s), __ldg(win + s + 1));
                }
            }
        }
    };

    // ---- CTA 0: prep (sort / tile table / t2 / out init) ----
    if (p == 0) {
        __shared__ int   warp_tot[8][NK];
        __shared__ int   warp_base[8][NK];
        __shared__ int   tot[NK];
        __shared__ int   base[NK];
        __shared__ float t2s[NK];

        {   // t2[k]: one warp per k
            float s = 0.f;
#pragma unroll
            for (int hh = 0; hh < 2; hh++) {
                int h = lane + hh * 32;
                float v = W2[h * NK + wid] + b2[h];
                s += fmaxf(v, 0.f) * W3[DIM + h];
            }
#pragma unroll
            for (int off = 16; off >= 1; off >>= 1)
                s += __shfl_xor_sync(0xFFFFFFFFu, s, off);
            if (lane == 0) t2s[wid] = s;
        }

        int myk[16];
#pragma unroll
        for (int i = 0; i < 16; i++) {
            int b = t * 16 + i;
            const float4* pp = (const float4*)(intention + (size_t)b * NK);
            float4 v0 = pp[0], v1 = pp[1];
            int k = 0;
            if (v0.y > 0.5f) k = 1;
            if (v0.z > 0.5f) k = 2;
            if (v0.w > 0.5f) k = 3;
            if (v1.x > 0.5f) k = 4;
            if (v1.y > 0.5f) k = 5;
            if (v1.z > 0.5f) k = 6;
            if (v1.w > 0.5f) k = 7;
            myk[i] = k;
        }
        int cntk[NK];
#pragma unroll
        for (int kk = 0; kk < NK; kk++) cntk[kk] = 0;
#pragma unroll
        for (int i = 0; i < 16; i++)
#pragma unroll
            for (int kk = 0; kk < NK; kk++) cntk[kk] += (myk[i] == kk) ? 1 : 0;
        int prelane[NK];
#pragma unroll
        for (int kk = 0; kk < NK; kk++) {
            int c = cntk[kk];
#pragma unroll
            for (int off = 1; off < 32; off <<= 1) {
                int v = __shfl_up_sync(0xFFFFFFFFu, c, off);
                if (lane >= off) c += v;
            }
            prelane[kk] = c - cntk[kk];
            if (lane == 31) warp_tot[wid][kk] = c;
        }
        __syncthreads();
        if (wid == 0 && lane < NK) {
            int s = 0;
#pragma unroll
            for (int ww = 0; ww < 8; ww++) {
                warp_base[ww][lane] = s;
                s += warp_tot[ww][lane];
            }
            tot[lane] = s;
        }
        __syncthreads();
        if (t == 0) {
            int off = 0, nt = 0;
            for (int k = 0; k < NK; k++) {
                base[k] = off;
                int c = tot[k];
                for (int r = 0; r < c; r += BM) {
                    g_tile_k[nt] = k;
                    g_tile_row0[nt] = off + r;
                    g_tile_rend[nt] = off + c;
                    nt++;
                }
                off += c;
            }
            g_ntiles = nt;
        }
        __syncthreads();
        float bias = b3[0];
        int run[NK];
#pragma unroll
        for (int kk = 0; kk < NK; kk++) run[kk] = 0;
#pragma unroll
        for (int i = 0; i < 16; i++) {
            int k = myk[i];
            int pos = 0;
            float t2v = 0.f;
#pragma unroll
            for (int kk = 0; kk < NK; kk++) {
                if (k == kk) {
                    pos = base[kk] + warp_base[wid][kk] + prelane[kk] + run[kk];
                    run[kk]++;
                    t2v = t2s[kk];
                }
            }
            int b = t * 16 + i;
            g_perm[pos] = b;
            out[b] = bias + t2v;
        }
        __threadfence();
        __syncthreads();
        if (t == 0) atomicExch(&g_prep, 1);
    }

    // ---- gemm static data ----
    extern __shared__ char smem[];
    uint32_t sb = smem_u32(smem);
    int mw = wid & 1;              // 2 warp-rows of 32
    int nw = wid >> 1;             // 4 warp-cols of 32

    int g       = lane >> 3;
    uint32_t xr = (uint32_t)(lane & 7);
    uint32_t a_row  = (uint32_t)(mw * 32 + (lane & 7) + 8 * (g & 1));
    uint32_t a_slot = (uint32_t)(g >> 1);
    uint32_t b_row  = (uint32_t)(nw * 32 + (lane & 7) + 8 * (g >> 1));
    uint32_t b_slot = (uint32_t)(g & 1);

    bool gated = false;

    // ---- job loop: jobs p, p+444, p+888 ----
    for (int jj = 0; jj < 3; jj++) {
        int job = p + jj * NCTA;
        if (job >= NJOBS) break;
        bool do_cvt = (jj == 0);

        if (do_cvt) {
            cvt_share(0);
            __threadfence();
            __syncthreads();
            if (t == 0) atomicAdd(&g_done[0], 1);
            cvt_share(1);
            __threadfence();
            __syncthreads();
            if (t == 0) atomicAdd(&g_done[1], 1);
        }
        if (!gated) {
            if (t == 0) {
                while (*(volatile int*)&g_prep < 1) __nanosleep(128);
            }
            __syncthreads();
            __threadfence();
            gated = true;
        }

        int tile = job % GYT;
        int dblk = job / GYT;
        bool active = (tile < g_ntiles);
        if (!active) {
            if (do_cvt) {
                for (int jc = 2; jc < NCHUNK; jc++) {
                    cvt_share(jc);
                    __threadfence();
                    __syncthreads();
                    if (t == 0) atomicAdd(&g_done[jc], 1);
                }
            }
            continue;
        }

        int k     = g_tile_k[tile];
        int row0  = g_tile_row0[tile];
        int rend  = g_tile_rend[tile];
        int dbase = dblk * BN;

        // A loader: 2 granules per thread
        const uint4* ah[2];
        uint32_t adst[2];
#pragma unroll
        for (int j = 0; j < 2; j++) {
            int idx  = t + j * 256;
            int row  = idx >> 3, gran = idx & 7;
            int pr   = row0 + row;
            int samp = (pr < rend) ? g_perm[pr] : g_perm[row0];
            ah[j]   = g_xh + (size_t)samp * (DIM / 8) + gran;
            adst[j] = (uint32_t)row * ROW_B + (uint32_t)((gran ^ (row & 7)) << 4);
        }
        // B loader: 4 granules per thread
        const uint4* bw = g_wh + ((size_t)k * DIM + dbase) * (DIM / 8);
        uint32_t boff[4], bdst[4];
#pragma unroll
        for (int j = 0; j < 4; j++) {
            int idx = t + j * 256;
            int row = idx >> 3, gran = idx & 7;
            boff[j] = (uint32_t)row * (DIM / 8) + (uint32_t)gran;
            bdst[j] = (uint32_t)row * ROW_B + (uint32_t)((gran ^ (row & 7)) << 4);
        }

        float acc[2][4][4];
#pragma unroll
        for (int i = 0; i < 2; i++)
#pragma unroll
            for (int j = 0; j < 4; j++)
#pragma unroll
                for (int e = 0; e < 4; e++) acc[i][j][e] = 0.f;

        auto issue = [&](int c, uint32_t st) {
            if (c < NCHUNK) {
                uint32_t c8 = (uint32_t)c * 8u;
                cpasync16(st + adst[0], ah[0] + c8);
                cpasync16(st + adst[1], ah[1] + c8);
#pragma unroll
                for (int j = 0; j < 4; j++)
                    cpasync16(st + A_T + bdst[j], bw + boff[j] + c8);
            }
            CP_COMMIT();
        };

        // prologue: wait chunks 0,1 ready, stage them
        if (t == 0) {
            while (*(volatile int*)&g_done[0] < NCTA) __nanosleep(64);
            while (*(volatile int*)&g_done[1] < NCTA) __nanosleep(64);
        }
        __syncthreads();
        __threadfence();
        issue(0, sb);
        issue(1, sb + STAGE_B);

        int cs = 0, is = 2;
#pragma unroll 1
        for (int c = 0; c < NCHUNK; c++) {
            CP_WAIT1();
            int nc = c + 2;
            if (do_cvt && nc < NCHUNK) {
                cvt_share(nc);
                __threadfence();
            }
            __syncthreads();
            if (t == 0 && nc < NCHUNK) {
                if (do_cvt) atomicAdd(&g_done[nc], 1);
                while (*(volatile int*)&g_done[nc] < NCTA) __nanosleep(64);
            }
            __syncthreads();
            issue(nc, sb + (uint32_t)is * STAGE_B);
            uint32_t st = sb + (uint32_t)cs * STAGE_B;

#pragma unroll
            for (int ks = 0; ks < 4; ks++) {
                uint32_t ka = (uint32_t)(((2 * ks + a_slot) ^ xr) << 4);
                uint32_t kb = (uint32_t)(((2 * ks + b_slot) ^ xr) << 4);
                uint32_t Ah[2][4];
#pragma unroll
                for (int i = 0; i < 2; i++)
                    ldsm4(Ah[i], st + (a_row + (uint32_t)i * 16u) * ROW_B + ka);
#pragma unroll
                for (int jp = 0; jp < 2; jp++) {
                    uint32_t B[4];
                    ldsm4(B, st + A_T + (b_row + (uint32_t)jp * 16u) * ROW_B + kb);
#pragma unroll
                    for (int i = 0; i < 2; i++) {
                        mma_f16(acc[i][jp * 2],     Ah[i], &B[0]);
                        mma_f16(acc[i][jp * 2 + 1], Ah[i], &B[2]);
                    }
                }
            }
            cs = (cs == 2) ? 0 : cs + 1;
            is = (is == 2) ? 0 : is + 1;
        }

        // epilogue
#pragma unroll
        for (int i = 0; i < 2; i++) {
            float s0 = 0.f, s1 = 0.f;
#pragma unroll
            for (int j = 0; j < 4; j++) {
                int d = dbase + nw * 32 + j * 8 + 2 * (lane & 3);
                float bb0 = __ldg(&b1[(size_t)d * NK + k]);
                float bb1 = __ldg(&b1[(size_t)(d + 1) * NK + k]);
                float w30 = __ldg(&W3[d]);
                float w31 = __ldg(&W3[d + 1]);
                s0 = fmaf(fmaxf(acc[i][j][0] + bb0, 0.f), w30, s0);
                s0 = fmaf(fmaxf(acc[i][j][1] + bb1, 0.f), w31, s0);
                s1 = fmaf(fmaxf(acc[i][j][2] + bb0, 0.f), w30, s1);
                s1 = fmaf(fmaxf(acc[i][j][3] + bb1, 0.f), w31, s1);
            }
            s0 += __shfl_xor_sync(0xFFFFFFFFu, s0, 1);
            s0 += __shfl_xor_sync(0xFFFFFFFFu, s0, 2);
            s1 += __shfl_xor_sync(0xFFFFFFFFu, s1, 1);
            s1 += __shfl_xor_sync(0xFFFFFFFFu, s1, 2);
            if ((lane & 3) == 0) {
                int m0 = mw * 32 + i * 16 + (lane >> 2);
                int pr0 = row0 + m0;
                int pr1 = pr0 + 8;
                if (pr0 < rend) atomicAdd(&out[g_perm[pr0]], s0);
                if (pr1 < rend) atomicAdd(&out[g_perm[pr1]], s1);
            }
        }
        __syncthreads();
    }
}

// ---------------- launch ----------------
extern "C" void kernel_launch(void* const* d_in, const int* in_sizes, int n_in,
                              void* d_out, int out_size) {
    const float* x         = (const float*)d_in[0];
    const float* intention = (const float*)d_in[1];
    const float* W1        = (const float*)d_in[2];
    const float* b1        = (const float*)d_in[3];
    const float* W2        = (const float*)d_in[4];
    const float* b2        = (const float*)d_in[5];
    const float* W3        = (const float*)d_in[6];
    const float* b3        = (const float*)d_in[7];
    float* out             = (float*)d_out;

    cudaFuncSetAttribute(fused_kernel, cudaFuncAttributeMaxDynamicSharedMemorySize,
                         SMEM_TOTAL);

    reset_kernel<<<1, 64>>>();
    fused_kernel<<<NCTA, 256, SMEM_TOTAL>>>(x, W1, intention, W2, b2, b1, W3, b3, out);
}

// round 16
// speedup vs baseline: 1.5766x; 1.5766x over previous
#include <cuda_runtime.h>
#include <cuda_fp16.h>
#include <cstdint>

// ---------------- problem constants ----------------
#define BATCH 4096
#define DIM   2048
#define NK    8
#define H2    64

// ---------------- tiling ----------------
#define BM     64
#define BN     128
#define KC     64
#define NCHUNK (DIM / KC)        // 32
#define GX     (DIM / BN)        // 16 d-blocks
#define GYT    72                // max m-tiles
#define NSTAGE 3
#define NCTA_G 444               // persistent gemm CTAs (3/SM x 148)

// 128-byte rows, XOR-swizzled (Swizzle<3,4,3>), no padding
#define ROW_B   128
#define A_T     (BM * ROW_B)     // 8192
#define B_T     (BN * ROW_B)     // 16384
#define STAGE_B (A_T + B_T)      // 24576
#define SMEM_TOTAL (NSTAGE * STAGE_B)   // 73728 (x3 CTAs = 221184 <= 228KB/SM)

// cvt work decomposition (unit = one output uint4 = 8 fp16)
#define XUNITS (BATCH * DIM / 8)              // 1048576
#define WUNITS ((size_t)NK * DIM * DIM / 8)   // 4194304
#define TUNITS (XUNITS + WUNITS)              // 5242880
#define NCVT   2048                           // cvt blocks

// ---------------- device scratch (no allocation allowed) ----------------
__device__ int g_perm[BATCH];
__device__ int g_tile_k[GYT];
__device__ int g_tile_row0[GYT];
__device__ int g_tile_rend[GYT];
__device__ int g_ntiles;
__device__ int g_ticket;
// pre-converted fp16 operands (packed uint4 = 8 elements)
__device__ uint4 g_xh[XUNITS];                // 16.8 MB
__device__ uint4 g_wh[WUNITS];                // 67 MB, regrouped [k][d][j]

// ---------------- PTX helpers ----------------
__device__ __forceinline__ uint32_t smem_u32(const void* p) {
    uint32_t a;
    asm("{ .reg .u64 t; cvta.to.shared.u64 t, %1; cvt.u32.u64 %0, t; }" : "=r"(a) : "l"(p));
    return a;
}

__device__ __forceinline__ void cpasync16(uint32_t dst, const void* src) {
    asm volatile("{ .reg .u64 g; cvta.to.global.u64 g, %1; "
                 "cp.async.cg.shared.global [%0], [g], 16; }"
                 :: "r"(dst), "l"(src) : "memory");
}
#define CP_COMMIT() asm volatile("cp.async.commit_group;" ::: "memory")
#define CP_WAIT1()  asm volatile("cp.async.wait_group 1;" ::: "memory")

__device__ __forceinline__ void ldsm4(uint32_t* r, uint32_t addr) {
    asm volatile("ldmatrix.sync.aligned.m8n8.x4.shared.b16 {%0,%1,%2,%3}, [%4];"
                 : "=r"(r[0]), "=r"(r[1]), "=r"(r[2]), "=r"(r[3]) : "r"(addr));
}

__device__ __forceinline__ void mma_f16(float* c, const uint32_t* a, const uint32_t* b) {
    asm volatile(
        "mma.sync.aligned.m16n8k16.row.col.f32.f16.f16.f32 "
        "{%0,%1,%2,%3}, {%4,%5,%6,%7}, {%8,%9}, {%0,%1,%2,%3};"
        : "+f"(c[0]), "+f"(c[1]), "+f"(c[2]), "+f"(c[3])
        : "r"(a[0]), "r"(a[1]), "r"(a[2]), "r"(a[3]), "r"(b[0]), "r"(b[1]));
}

__device__ __forceinline__ uint32_t packh2(float f0, float f1) {
    __half2 p = __floats2half2_rn(f0, f1);
    return *reinterpret_cast<uint32_t*>(&p);
}

__device__ __forceinline__ uint4 pack8(float4 v0, float4 v1) {
    uint4 h;
    h.x = packh2(v0.x, v0.y);
    h.y = packh2(v0.z, v0.w);
    h.z = packh2(v1.x, v1.y);
    h.w = packh2(v1.z, v1.w);
    return h;
}

// ---------------- merged prepass ----------------
// block 0          : atomic-free sort/tile-table/t2/out-init + ticket reset
// blocks 1..NCVT   : grid-stride fp32->fp16 conversion of x and W1
__global__ void __launch_bounds__(256) prep_cvt_kernel(
    const float* __restrict__ x, const float* __restrict__ W1,
    const float* __restrict__ intention, const float* __restrict__ W2,
    const float* __restrict__ b2, const float* __restrict__ W3,
    const float* __restrict__ b3, float* __restrict__ out) {
    int blk = blockIdx.x;
    int t   = threadIdx.x;

    if (blk > 0) {
        // ---- grid-stride converter ----
        const float4* xin = (const float4*)x;
        const float4* win = (const float4*)W1;
        size_t stride = (size_t)NCVT * 256;
        size_t u0 = (size_t)(blk - 1) * 256 + t;
#pragma unroll 2
        for (size_t u = u0; u < TUNITS; u += stride) {
            if (u < XUNITS) {
                g_xh[u] = pack8(__ldg(xin + 2 * u), __ldg(xin + 2 * u + 1));
            } else {
                size_t v = u - XUNITS;
                int k = (int)(v >> 19);               // DIM*DIM/8 = 2^19
                int d = (int)((v >> 8) & (DIM - 1));
                int j = (int)(v & 255);
                size_t src = ((size_t)((d << 3) | k)) * (DIM / 4) + 2 * j;
                g_wh[v] = pack8(__ldg(win + src), __ldg(win + src + 1));
            }
        }
        return;
    }

    // ---- prep block (blk == 0) ----
    __shared__ int   warp_tot[8][NK];
    __shared__ int   warp_base[8][NK];
    __shared__ int   tot[NK];
    __shared__ int   base[NK];
    __shared__ float t2s[NK];
    int lane = t & 31, w = t >> 5;

    if (t == 0) g_ticket = 0;       // reset work-stealing ticket each launch

    // t2[k]: one warp per k, lanes split the 64 h-terms
    {
        float s = 0.f;
#pragma unroll
        for (int hh = 0; hh < 2; hh++) {
            int h = lane + hh * 32;
            float v = W2[h * NK + w] + b2[h];
            s += fmaxf(v, 0.f) * W3[DIM + h];
        }
#pragma unroll
        for (int off = 16; off >= 1; off >>= 1)
            s += __shfl_xor_sync(0xFFFFFFFFu, s, off);
        if (lane == 0) t2s[w] = s;
    }

    int myk[16];
#pragma unroll
    for (int i = 0; i < 16; i++) {
        int b = t * 16 + i;
        const float4* p = (const float4*)(intention + (size_t)b * NK);
        float4 v0 = p[0], v1 = p[1];
        int k = 0;
        if (v0.y > 0.5f) k = 1;
        if (v0.z > 0.5f) k = 2;
        if (v0.w > 0.5f) k = 3;
        if (v1.x > 0.5f) k = 4;
        if (v1.y > 0.5f) k = 5;
        if (v1.z > 0.5f) k = 6;
        if (v1.w > 0.5f) k = 7;
        myk[i] = k;
    }

    int cntk[NK];
#pragma unroll
    for (int kk = 0; kk < NK; kk++) cntk[kk] = 0;
#pragma unroll
    for (int i = 0; i < 16; i++)
#pragma unroll
        for (int kk = 0; kk < NK; kk++) cntk[kk] += (myk[i] == kk) ? 1 : 0;

    int prelane[NK];
#pragma unroll
    for (int kk = 0; kk < NK; kk++) {
        int c = cntk[kk];
#pragma unroll
        for (int off = 1; off < 32; off <<= 1) {
            int v = __shfl_up_sync(0xFFFFFFFFu, c, off);
            if (lane >= off) c += v;
        }
        prelane[kk] = c - cntk[kk];
        if (lane == 31) warp_tot[w][kk] = c;
    }
    __syncthreads();

    if (w == 0 && lane < NK) {
        int s = 0;
#pragma unroll
        for (int ww = 0; ww < 8; ww++) {
            warp_base[ww][lane] = s;
            s += warp_tot[ww][lane];
        }
        tot[lane] = s;
    }
    __syncthreads();

    if (t == 0) {
        int off = 0, nt = 0;
        for (int k = 0; k < NK; k++) {
            base[k] = off;
            int c = tot[k];
            for (int r = 0; r < c; r += BM) {
                g_tile_k[nt] = k;
                g_tile_row0[nt] = off + r;
                g_tile_rend[nt] = off + c;
                nt++;
            }
            off += c;
        }
        g_ntiles = nt;
    }
    __syncthreads();

    float bias = b3[0];
    int run[NK];
#pragma unroll
    for (int kk = 0; kk < NK; kk++) run[kk] = 0;
#pragma unroll
    for (int i = 0; i < 16; i++) {
        int k = myk[i];
        int pos = 0;
        float t2v = 0.f;
#pragma unroll
        for (int kk = 0; kk < NK; kk++) {
            if (k == kk) {
                pos = base[kk] + warp_base[w][kk] + prelane[kk] + run[kk];
                run[kk]++;
                t2v = t2s[kk];
            }
        }
        int b = t * 16 + i;
        g_perm[pos] = b;
        out[b] = bias + t2v;
    }
}

// ---------------- persistent work-stealing HMMA GEMM ----------------
__global__ void __launch_bounds__(256, 3) gemm_kernel(
    const float* __restrict__ b1, const float* __restrict__ W3,
    float* __restrict__ out) {
    extern __shared__ char smem[];
    __shared__ int s_job;
    uint32_t sb = smem_u32(smem);
    int t    = threadIdx.x;
    int lane = t & 31;
    int wid  = t >> 5;
    int mw   = wid & 1;            // 2 warp-rows of 32
    int nw   = wid >> 1;           // 4 warp-cols of 32

    // ---- ldmatrix lane mapping (job-invariant) ----
    int g       = lane >> 3;
    uint32_t xr = (uint32_t)(lane & 7);
    uint32_t a_row  = (uint32_t)(mw * 32 + (lane & 7) + 8 * (g & 1));
    uint32_t a_slot = (uint32_t)(g >> 1);
    uint32_t b_row  = (uint32_t)(nw * 32 + (lane & 7) + 8 * (g >> 1));
    uint32_t b_slot = (uint32_t)(g & 1);

    int nt = g_ntiles;
    int njobs = nt * GX;

    for (;;) {
        if (t == 0) s_job = atomicAdd(&g_ticket, 1);
        __syncthreads();
        int job = s_job;
        if (job >= njobs) break;
        int tile = job % nt;
        int dblk = job / nt;

        int k     = g_tile_k[tile];
        int row0  = g_tile_row0[tile];
        int rend  = g_tile_rend[tile];
        int dbase = dblk * BN;

        // ---- A loader: 2 granules per thread ----
        const uint4* ah[2];
        uint32_t adst[2];
#pragma unroll
        for (int j = 0; j < 2; j++) {
            int idx  = t + j * 256;
            int row  = idx >> 3, gran = idx & 7;
            int pr   = row0 + row;
            int samp = (pr < rend) ? g_perm[pr] : g_perm[row0];
            ah[j]   = g_xh + (size_t)samp * (DIM / 8) + gran;
            adst[j] = (uint32_t)row * ROW_B + (uint32_t)((gran ^ (row & 7)) << 4);
        }
        // ---- B loader: 4 granules per thread ----
        const uint4* bw = g_wh + ((size_t)k * DIM + dbase) * (DIM / 8);
        uint32_t boff[4], bdst[4];
#pragma unroll
        for (int j = 0; j < 4; j++) {
            int idx = t + j * 256;
            int row = idx >> 3, gran = idx & 7;
            boff[j] = (uint32_t)row * (DIM / 8) + (uint32_t)gran;
            bdst[j] = (uint32_t)row * ROW_B + (uint32_t)((gran ^ (row & 7)) << 4);
        }

        float acc[2][4][4];
#pragma unroll
        for (int i = 0; i < 2; i++)
#pragma unroll
            for (int j = 0; j < 4; j++)
#pragma unroll
                for (int e = 0; e < 4; e++) acc[i][j][e] = 0.f;

        auto issue = [&](int c, uint32_t st) {
            if (c < NCHUNK) {
                uint32_t c8 = (uint32_t)c * 8u;
                cpasync16(st + adst[0], ah[0] + c8);
                cpasync16(st + adst[1], ah[1] + c8);
#pragma unroll
                for (int j = 0; j < 4; j++)
                    cpasync16(st + A_T + bdst[j], bw + boff[j] + c8);
            }
            CP_COMMIT();
        };

        issue(0, sb);
        issue(1, sb + STAGE_B);

        int cs = 0;   // compute stage
        int is = 2;   // issue stage
#pragma unroll 1
        for (int c = 0; c < NCHUNK; c++) {
            CP_WAIT1();
            __syncthreads();
            issue(c + 2, sb + (uint32_t)is * STAGE_B);
            uint32_t st = sb + (uint32_t)cs * STAGE_B;

#pragma unroll
            for (int ks = 0; ks < 4; ks++) {
                uint32_t ka = (uint32_t)(((2 * ks + a_slot) ^ xr) << 4);
                uint32_t kb = (uint32_t)(((2 * ks + b_slot) ^ xr) << 4);
                uint32_t Ah[2][4];
#pragma unroll
                for (int i = 0; i < 2; i++)
                    ldsm4(Ah[i], st + (a_row + (uint32_t)i * 16u) * ROW_B + ka);
#pragma unroll
                for (int jp = 0; jp < 2; jp++) {
                    uint32_t B[4];
                    ldsm4(B, st + A_T + (b_row + (uint32_t)jp * 16u) * ROW_B + kb);
#pragma unroll
                    for (int i = 0; i < 2; i++) {
                        mma_f16(acc[i][jp * 2],     Ah[i], &B[0]);
                        mma_f16(acc[i][jp * 2 + 1], Ah[i], &B[2]);
                    }
                }
            }
            cs = (cs == 2) ? 0 : cs + 1;
            is = (is == 2) ? 0 : is + 1;
        }

        // ---- fused epilogue: relu(acc + b1) * W3, row-reduce, atomicAdd ----
#pragma unroll
        for (int i = 0; i < 2; i++) {
            float s0 = 0.f, s1 = 0.f;
#pragma unroll
            for (int j = 0; j < 4; j++) {
                int d = dbase + nw * 32 + j * 8 + 2 * (lane & 3);
                float bb0 = __ldg(&b1[(size_t)d * NK + k]);
                float bb1 = __ldg(&b1[(size_t)(d + 1) * NK + k]);
                float w30 = __ldg(&W3[d]);
                float w31 = __ldg(&W3[d + 1]);
                s0 = fmaf(fmaxf(acc[i][j][0] + bb0, 0.f), w30, s0);
                s0 = fmaf(fmaxf(acc[i][j][1] + bb1, 0.f), w31, s0);
                s1 = fmaf(fmaxf(acc[i][j][2] + bb0, 0.f), w30, s1);
                s1 = fmaf(fmaxf(acc[i][j][3] + bb1, 0.f), w31, s1);
            }
            s0 += __shfl_xor_sync(0xFFFFFFFFu, s0, 1);
            s0 += __shfl_xor_sync(0xFFFFFFFFu, s0, 2);
            s1 += __shfl_xor_sync(0xFFFFFFFFu, s1, 1);
            s1 += __shfl_xor_sync(0xFFFFFFFFu, s1, 2);
            if ((lane & 3) == 0) {
                int m0 = mw * 32 + i * 16 + (lane >> 2);
                int pr0 = row0 + m0;
                int pr1 = pr0 + 8;
                if (pr0 < rend) atomicAdd(&out[g_perm[pr0]], s0);
                if (pr1 < rend) atomicAdd(&out[g_perm[pr1]], s1);
            }
        }
        __syncthreads();   // protect s_job + smem stages before next job
    }
}

// ---------------- launch ----------------
extern "C" void kernel_launch(void* const* d_in, const int* in_sizes, int n_in,
                              void* d_out, int out_size) {
    const float* x         = (const float*)d_in[0];
    const float* intention = (const float*)d_in[1];
    const float* W1        = (const float*)d_in[2];
    const float* b1        = (const float*)d_in[3];
    const float* W2        = (const float*)d_in[4];
    const float* b2        = (const float*)d_in[5];
    const float* W3        = (const float*)d_in[6];
    const float* b3        = (const float*)d_in[7];
    float* out             = (float*)d_out;

    cudaFuncSetAttribute(gemm_kernel, cudaFuncAttributeMaxDynamicSharedMemorySize,
                         SMEM_TOTAL);

    prep_cvt_kernel<<<NCVT + 1, 256>>>(x, W1, intention, W2, b2, W3, b3, out);
    gemm_kernel<<<NCTA_G, 256, SMEM_TOTAL>>>(b1, W3, out);
}

// round 17
// speedup vs baseline: 1.8951x; 1.2020x over previous
#include <cuda_runtime.h>
#include <cuda_fp16.h>
#include <cstdint>

// ---------------- problem constants ----------------
#define BATCH 4096
#define DIM   2048
#define NK    8
#define H2    64

// ---------------- tiling ----------------
#define BM     64
#define BN     128
#define KC     64
#define NCHUNK (DIM / KC)        // 32
#define GX     (DIM / BN)        // 16 d-blocks
#define GYT    72                // max m-tiles (worst case 64+8)
#define NSTAGE 3

// 128-byte rows, XOR-swizzled (Swizzle<3,4,3>), no padding
#define ROW_B   128
#define A_T     (BM * ROW_B)     // 8192
#define B_T     (BN * ROW_B)     // 16384
#define STAGE_B (A_T + B_T)      // 24576
#define SMEM_TOTAL (NSTAGE * STAGE_B)   // 73728 (x3 CTAs = 221184 <= 228KB/SM)

// cvt work decomposition (unit = one output uint4 = 8 fp16)
#define XUNITS (BATCH * DIM / 8)              // 1048576
#define WUNITS ((size_t)NK * DIM * DIM / 8)   // 4194304
#define TUNITS (XUNITS + WUNITS)              // 5242880
#define NCVT   2048                           // cvt blocks (10 units/thread)

// ---------------- device scratch (no allocation allowed) ----------------
__device__ int g_perm[BATCH];
__device__ int g_tile_k[GYT];
__device__ int g_tile_row0[GYT];
__device__ int g_tile_rend[GYT];
__device__ int g_ntiles;
__device__ float g_b1g[NK * DIM];             // b1 regrouped [k][d], 64KB
// pre-converted fp16 operands (packed uint4 = 8 elements)
__device__ uint4 g_xh[XUNITS];                // 16.8 MB
__device__ uint4 g_wh[WUNITS];                // 67 MB, regrouped [k][d][j]

// ---------------- PTX helpers ----------------
__device__ __forceinline__ uint32_t smem_u32(const void* p) {
    uint32_t a;
    asm("{ .reg .u64 t; cvta.to.shared.u64 t, %1; cvt.u32.u64 %0, t; }" : "=r"(a) : "l"(p));
    return a;
}

__device__ __forceinline__ void cpasync16(uint32_t dst, const void* src) {
    asm volatile("{ .reg .u64 g; cvta.to.global.u64 g, %1; "
                 "cp.async.cg.shared.global [%0], [g], 16; }"
                 :: "r"(dst), "l"(src) : "memory");
}
#define CP_COMMIT() asm volatile("cp.async.commit_group;" ::: "memory")
#define CP_WAIT1()  asm volatile("cp.async.wait_group 1;" ::: "memory")

__device__ __forceinline__ void ldsm4(uint32_t* r, uint32_t addr) {
    asm volatile("ldmatrix.sync.aligned.m8n8.x4.shared.b16 {%0,%1,%2,%3}, [%4];"
                 : "=r"(r[0]), "=r"(r[1]), "=r"(r[2]), "=r"(r[3]) : "r"(addr));
}

__device__ __forceinline__ void mma_f16(float* c, const uint32_t* a, const uint32_t* b) {
    asm volatile(
        "mma.sync.aligned.m16n8k16.row.col.f32.f16.f16.f32 "
        "{%0,%1,%2,%3}, {%4,%5,%6,%7}, {%8,%9}, {%0,%1,%2,%3};"
        : "+f"(c[0]), "+f"(c[1]), "+f"(c[2]), "+f"(c[3])
        : "r"(a[0]), "r"(a[1]), "r"(a[2]), "r"(a[3]), "r"(b[0]), "r"(b[1]));
}

__device__ __forceinline__ uint32_t packh2(float f0, float f1) {
    __half2 p = __floats2half2_rn(f0, f1);
    return *reinterpret_cast<uint32_t*>(&p);
}

__device__ __forceinline__ uint4 pack8(float4 v0, float4 v1) {
    uint4 h;
    h.x = packh2(v0.x, v0.y);
    h.y = packh2(v0.z, v0.w);
    h.z = packh2(v1.x, v1.y);
    h.w = packh2(v1.z, v1.w);
    return h;
}

// ---------------- merged prepass ----------------
// block 0          : atomic-free sort/tile-table/t2/out-init + b1 regroup
// blocks 1..NCVT   : grid-stride fp32->fp16 conversion of x and W1
__global__ void __launch_bounds__(256) prep_cvt_kernel(
    const float* __restrict__ x, const float* __restrict__ W1,
    const float* __restrict__ intention, const float* __restrict__ W2,
    const float* __restrict__ b2, const float* __restrict__ W3,
    const float* __restrict__ b3, const float* __restrict__ b1,
    float* __restrict__ out) {
    int blk = blockIdx.x;
    int t   = threadIdx.x;

    if (blk > 0) {
        // ---- grid-stride converter ----
        const float4* xin = (const float4*)x;
        const float4* win = (const float4*)W1;
        size_t stride = (size_t)NCVT * 256;
        size_t u0 = (size_t)(blk - 1) * 256 + t;
#pragma unroll 2
        for (size_t u = u0; u < TUNITS; u += stride) {
            if (u < XUNITS) {
                g_xh[u] = pack8(__ldg(xin + 2 * u), __ldg(xin + 2 * u + 1));
            } else {
                size_t v = u - XUNITS;
                int k = (int)(v >> 19);               // DIM*DIM/8 = 2^19
                int d = (int)((v >> 8) & (DIM - 1));
                int j = (int)(v & 255);
                size_t src = ((size_t)((d << 3) | k)) * (DIM / 4) + 2 * j;
                g_wh[v] = pack8(__ldg(win + src), __ldg(win + src + 1));
            }
        }
        return;
    }

    // ---- prep block (blk == 0) ----
    __shared__ int   warp_tot[8][NK];
    __shared__ int   warp_base[8][NK];
    __shared__ int   tot[NK];
    __shared__ int   base[NK];
    __shared__ float t2s[NK];
    int lane = t & 31, w = t >> 5;

    // b1 regroup: b1g[k][d] = b1[d*8+k]; 64 elements per thread, coalesced reads
    {
#pragma unroll
        for (int i = 0; i < 16; i++) {
            int r4 = t * 16 + i;                 // float4 index into b1 (4096 total)
            float4 v = __ldg((const float4*)b1 + r4);
            int r = r4 * 4;                      // element = d*8+k
            g_b1g[(r & 7) * DIM + (r >> 3)]             = v.x;
            g_b1g[((r + 1) & 7) * DIM + ((r + 1) >> 3)] = v.y;
            g_b1g[((r + 2) & 7) * DIM + ((r + 2) >> 3)] = v.z;
            g_b1g[((r + 3) & 7) * DIM + ((r + 3) >> 3)] = v.w;
        }
    }

    // t2[k]: one warp per k, lanes split the 64 h-terms
    {
        float s = 0.f;
#pragma unroll
        for (int hh = 0; hh < 2; hh++) {
            int h = lane + hh * 32;
            float v = W2[h * NK + w] + b2[h];
            s += fmaxf(v, 0.f) * W3[DIM + h];
        }
#pragma unroll
        for (int off = 16; off >= 1; off >>= 1)
            s += __shfl_xor_sync(0xFFFFFFFFu, s, off);
        if (lane == 0) t2s[w] = s;
    }

    int myk[16];
#pragma unroll
    for (int i = 0; i < 16; i++) {
        int b = t * 16 + i;
        const float4* p = (const float4*)(intention + (size_t)b * NK);
        float4 v0 = p[0], v1 = p[1];
        int k = 0;
        if (v0.y > 0.5f) k = 1;
        if (v0.z > 0.5f) k = 2;
        if (v0.w > 0.5f) k = 3;
        if (v1.x > 0.5f) k = 4;
        if (v1.y > 0.5f) k = 5;
        if (v1.z > 0.5f) k = 6;
        if (v1.w > 0.5f) k = 7;
        myk[i] = k;
    }

    int cntk[NK];
#pragma unroll
    for (int kk = 0; kk < NK; kk++) cntk[kk] = 0;
#pragma unroll
    for (int i = 0; i < 16; i++)
#pragma unroll
        for (int kk = 0; kk < NK; kk++) cntk[kk] += (myk[i] == kk) ? 1 : 0;

    int prelane[NK];
#pragma unroll
    for (int kk = 0; kk < NK; kk++) {
        int c = cntk[kk];
#pragma unroll
        for (int off = 1; off < 32; off <<= 1) {
            int v = __shfl_up_sync(0xFFFFFFFFu, c, off);
            if (lane >= off) c += v;
        }
        prelane[kk] = c - cntk[kk];
        if (lane == 31) warp_tot[w][kk] = c;
    }
    __syncthreads();

    if (w == 0 && lane < NK) {
        int s = 0;
#pragma unroll
        for (int ww = 0; ww < 8; ww++) {
            warp_base[ww][lane] = s;
            s += warp_tot[ww][lane];
        }
        tot[lane] = s;
    }
    __syncthreads();

    if (t == 0) {
        int off = 0, nt = 0;
        for (int k = 0; k < NK; k++) {
            base[k] = off;
            int c = tot[k];
            for (int r = 0; r < c; r += BM) {
                g_tile_k[nt] = k;
                g_tile_row0[nt] = off + r;
                g_tile_rend[nt] = off + c;
                nt++;
            }
            off += c;
        }
        g_ntiles = nt;
    }
    __syncthreads();

    float bias = b3[0];
    int run[NK];
#pragma unroll
    for (int kk = 0; kk < NK; kk++) run[kk] = 0;
#pragma unroll
    for (int i = 0; i < 16; i++) {
        int k = myk[i];
        int pos = 0;
        float t2v = 0.f;
#pragma unroll
        for (int kk = 0; kk < NK; kk++) {
            if (k == kk) {
                pos = base[kk] + warp_base[w][kk] + prelane[kk] + run[kk];
                run[kk]++;
                t2v = t2s[kk];
            }
        }
        int b = t * 16 + i;
        g_perm[pos] = b;
        out[b] = bias + t2v;
    }
}

// ---------------- fused grouped HMMA GEMM (fp16, KC=64 swizzled, 3 CTAs/SM) ----------------
__global__ void __launch_bounds__(256, 3) gemm_kernel(
    const float* __restrict__ W3, float* __restrict__ out) {
    int tile = blockIdx.x;
    if (tile >= g_ntiles) return;
    int k     = g_tile_k[tile];
    int row0  = g_tile_row0[tile];
    int rend  = g_tile_rend[tile];
    int dbase = blockIdx.y * BN;

    extern __shared__ char smem[];
    uint32_t sb = smem_u32(smem);
    int t    = threadIdx.x;
    int lane = t & 31;
    int wid  = t >> 5;
    int mw   = wid & 1;            // 2 warp-rows of 32
    int nw   = wid >> 1;           // 4 warp-cols of 32

    // ---- A loader: 2 granules per thread ----
    const uint4* ah[2];
    uint32_t adst[2];
#pragma unroll
    for (int j = 0; j < 2; j++) {
        int idx  = t + j * 256;
        int row  = idx >> 3, gran = idx & 7;
        int pr   = row0 + row;
        int samp = (pr < rend) ? g_perm[pr] : g_perm[row0];
        ah[j]   = g_xh + (size_t)samp * (DIM / 8) + gran;
        adst[j] = (uint32_t)row * ROW_B + (uint32_t)((gran ^ (row & 7)) << 4);
    }
    // ---- B loader: 4 granules per thread ----
    const uint4* bw = g_wh + ((size_t)k * DIM + dbase) * (DIM / 8);
    uint32_t boff[4], bdst[4];
#pragma unroll
    for (int j = 0; j < 4; j++) {
        int idx = t + j * 256;
        int row = idx >> 3, gran = idx & 7;
        boff[j] = (uint32_t)row * (DIM / 8) + (uint32_t)gran;
        bdst[j] = (uint32_t)row * ROW_B + (uint32_t)((gran ^ (row & 7)) << 4);
    }

    // ---- ldmatrix lane mapping (swizzled) ----
    int g       = lane >> 3;
    uint32_t xr = (uint32_t)(lane & 7);
    uint32_t a_row  = (uint32_t)(mw * 32 + (lane & 7) + 8 * (g & 1));
    uint32_t a_slot = (uint32_t)(g >> 1);
    uint32_t b_row  = (uint32_t)(nw * 32 + (lane & 7) + 8 * (g >> 1));
    uint32_t b_slot = (uint32_t)(g & 1);

    float acc[2][4][4];
#pragma unroll
    for (int i = 0; i < 2; i++)
#pragma unroll
        for (int j = 0; j < 4; j++)
#pragma unroll
            for (int e = 0; e < 4; e++) acc[i][j][e] = 0.f;

    auto issue = [&](int c, uint32_t st) {
        if (c < NCHUNK) {
            uint32_t c8 = (uint32_t)c * 8u;
            cpasync16(st + adst[0], ah[0] + c8);
            cpasync16(st + adst[1], ah[1] + c8);
#pragma unroll
            for (int j = 0; j < 4; j++)
                cpasync16(st + A_T + bdst[j], bw + boff[j] + c8);
        }
        CP_COMMIT();
    };

    issue(0, sb);
    issue(1, sb + STAGE_B);

    int cs = 0;   // compute stage
    int is = 2;   // issue stage
#pragma unroll 1
    for (int c = 0; c < NCHUNK; c++) {
        CP_WAIT1();
        __syncthreads();
        issue(c + 2, sb + (uint32_t)is * STAGE_B);
        uint32_t st = sb + (uint32_t)cs * STAGE_B;

#pragma unroll
        for (int ks = 0; ks < 4; ks++) {
            uint32_t ka = (uint32_t)(((2 * ks + a_slot) ^ xr) << 4);
            uint32_t kb = (uint32_t)(((2 * ks + b_slot) ^ xr) << 4);
            uint32_t Ah[2][4];
#pragma unroll
            for (int i = 0; i < 2; i++)
                ldsm4(Ah[i], st + (a_row + (uint32_t)i * 16u) * ROW_B + ka);
#pragma unroll
            for (int jp = 0; jp < 2; jp++) {
                uint32_t B[4];
                ldsm4(B, st + A_T + (b_row + (uint32_t)jp * 16u) * ROW_B + kb);
#pragma unroll
                for (int i = 0; i < 2; i++) {
                    mma_f16(acc[i][jp * 2],     Ah[i], &B[0]);
                    mma_f16(acc[i][jp * 2 + 1], Ah[i], &B[2]);
                }
            }
        }
        cs = (cs == 2) ? 0 : cs + 1;
        is = (is == 2) ? 0 : is + 1;
    }

    // ---- fused epilogue: relu(acc + b1) * W3, row-reduce, atomicAdd ----
    const float* b1k = g_b1g + k * DIM;
#pragma unroll
    for (int i = 0; i < 2; i++) {
        float s0 = 0.f, s1 = 0.f;
#pragma unroll
        for (int j = 0; j < 4; j++) {
            int d = dbase + nw * 32 + j * 8 + 2 * (lane & 3);
            float bb0 = __ldg(&b1k[d]);
            float bb1 = __ldg(&b1k[d + 1]);
            float w30 = __ldg(&W3[d]);
            float w31 = __ldg(&W3[d + 1]);
            s0 = fmaf(fmaxf(acc[i][j][0] + bb0, 0.f), w30, s0);
            s0 = fmaf(fmaxf(acc[i][j][1] + bb1, 0.f), w31, s0);
            s1 = fmaf(fmaxf(acc[i][j][2] + bb0, 0.f), w30, s1);
            s1 = fmaf(fmaxf(acc[i][j][3] + bb1, 0.f), w31, s1);
        }
        s0 += __shfl_xor_sync(0xFFFFFFFFu, s0, 1);
        s0 += __shfl_xor_sync(0xFFFFFFFFu, s0, 2);
        s1 += __shfl_xor_sync(0xFFFFFFFFu, s1, 1);
        s1 += __shfl_xor_sync(0xFFFFFFFFu, s1, 2);
        if ((lane & 3) == 0) {
            int m0 = mw * 32 + i * 16 + (lane >> 2);
            int pr0 = row0 + m0;
            int pr1 = pr0 + 8;
            if (pr0 < rend) atomicAdd(&out[g_perm[pr0]], s0);
            if (pr1 < rend) atomicAdd(&out[g_perm[pr1]], s1);
        }
    }
}

// ---------------- launch ----------------
extern "C" void kernel_launch(void* const* d_in, const int* in_sizes, int n_in,
                              void* d_out, int out_size) {
    const float* x         = (const float*)d_in[0];
    const float* intention = (const float*)d_in[1];
    const float* W1        = (const float*)d_in[2];
    const float* b1        = (const float*)d_in[3];
    const float* W2        = (const float*)d_in[4];
    const float* b2        = (const float*)d_in[5];
    const float* W3        = (const float*)d_in[6];
    const float* b3        = (const float*)d_in[7];
    float* out             = (float*)d_out;

    cudaFuncSetAttribute(gemm_kernel, cudaFuncAttributeMaxDynamicSharedMemorySize,
                         SMEM_TOTAL);

    prep_cvt_kernel<<<NCVT + 1, 256>>>(x, W1, intention, W2, b2, W3, b3, b1, out);
    gemm_kernel<<<dim3(GYT, GX), 256, SMEM_TOTAL>>>(W3, out);
}